// round 3
// baseline (speedup 1.0000x reference)
#include <cuda_runtime.h>

typedef unsigned long long ull;

#define NPTS 32768
#define CDIM 128
#define NSAM 16
#define CSD  16
#define PAIRS (NPTS*NSAM)
#define FEPS 1e-5f

// ---------------- scratch (device globals; no allocation allowed) ----------
__device__ float g_q[NPTS*CDIM];
__device__ float g_k[NPTS*CDIM];
__device__ float g_v[NPTS*CDIM];
__device__ float g_prlin[PAIRS*3];
__device__ float g_w2[PAIRS*CSD];

__device__ float g_s1[3],    g_ss1[3],    g_scale1[3],    g_shift1[3];
__device__ float g_s2[CDIM], g_ss2[CDIM], g_scale2[CDIM], g_shift2[CDIM];
__device__ float g_s3[CSD],  g_ss3[CSD],  g_scale3[CSD],  g_shift3[CSD];
__device__ unsigned g_tk1, g_tk2, g_tk3;

// ---------------- f32x2 helpers (used ONLY in k_w2 stage B) -----------------
__device__ __forceinline__ void upk2(float& lo, float& hi, ull v) {
    asm("mov.b64 {%0,%1},%2;" : "=f"(lo), "=f"(hi) : "l"(v));
}
__device__ __forceinline__ void fma2(ull& d, ull a, ull b) {
    asm("fma.rn.f32x2 %0,%1,%2,%0;" : "+l"(d) : "l"(a), "l"(b));
}
#define D2L(x) __double_as_longlong(x)

// ---------------- K1: zero stats + tickets ----------------------------------
__global__ void k_zero() {
    int t = threadIdx.x;
    if (t < 3)    { g_s1[t] = 0.f; g_ss1[t] = 0.f; }
    if (t < CDIM) { g_s2[t] = 0.f; g_ss2[t] = 0.f; }
    if (t < CSD)  { g_s3[t] = 0.f; g_ss3[t] = 0.f; }
    if (t == 0) { g_tk1 = 0; g_tk2 = 0; g_tk3 = 0; }
}

// ---------------- K2: q/k/v GEMMs (x[N,128] @ W[128,128] + b) ---------------
// grid (N/64, 3), block 256. BM=64, BN=128, BK=32. thread tile 8x4. (R1 form)
__global__ void k_qkv(const float* __restrict__ x,
                      const float* __restrict__ Wq, const float* __restrict__ bq,
                      const float* __restrict__ Wk, const float* __restrict__ bk,
                      const float* __restrict__ Wv, const float* __restrict__ bv) {
    const float* W; const float* b; float* out;
    if (blockIdx.y == 0)      { W = Wq; b = bq; out = g_q; }
    else if (blockIdx.y == 1) { W = Wk; b = bk; out = g_k; }
    else                      { W = Wv; b = bv; out = g_v; }

    __shared__ float xs[64*33];
    __shared__ float ws[32*132];

    int t  = threadIdx.x;
    int tx = t & 31, ty = t >> 5;
    int row0 = blockIdx.x * 64;

    float acc[8][4];
#pragma unroll
    for (int i = 0; i < 8; i++)
#pragma unroll
        for (int j = 0; j < 4; j++) acc[i][j] = 0.f;

    for (int kb = 0; kb < 128; kb += 32) {
#pragma unroll
        for (int e = t; e < 64*32; e += 256) {
            int r = e >> 5, c = e & 31;
            xs[r*33 + c] = x[(row0 + r)*128 + kb + c];
        }
#pragma unroll
        for (int e = t; e < 32*128; e += 256) {
            int r = e >> 7, c = e & 127;
            ws[r*132 + c] = W[(kb + r)*128 + c];
        }
        __syncthreads();
#pragma unroll
        for (int k = 0; k < 32; k++) {
            float4 wf = *(const float4*)&ws[k*132 + tx*4];
#pragma unroll
            for (int i = 0; i < 8; i++) {
                float xf = xs[(ty*8 + i)*33 + k];
                acc[i][0] += xf * wf.x;
                acc[i][1] += xf * wf.y;
                acc[i][2] += xf * wf.z;
                acc[i][3] += xf * wf.w;
            }
        }
        __syncthreads();
    }

    float b0 = b[tx*4+0], b1 = b[tx*4+1], b2 = b[tx*4+2], b3 = b[tx*4+3];
#pragma unroll
    for (int i = 0; i < 8; i++) {
        int r = row0 + ty*8 + i;
        float4 o;
        o.x = acc[i][0] + b0;
        o.y = acc[i][1] + b1;
        o.z = acc[i][2] + b2;
        o.w = acc[i][3] + b3;
        *(float4*)&out[r*128 + tx*4] = o;
    }
}

// ---------------- K3: prlin + BN1 stats + fused finalize --------------------
__global__ void k_prlin(const float* __restrict__ p, const int* __restrict__ idx,
                        const float* __restrict__ pW1, const float* __restrict__ pb1,
                        const float* __restrict__ g, const float* __restrict__ be) {
    float w00 = pW1[0], w01 = pW1[1], w02 = pW1[2];
    float w10 = pW1[3], w11 = pW1[4], w12 = pW1[5];
    float w20 = pW1[6], w21 = pW1[7], w22 = pW1[8];
    float b0 = pb1[0], b1 = pb1[1], b2 = pb1[2];

    float s[3]  = {0.f, 0.f, 0.f};
    float ss[3] = {0.f, 0.f, 0.f};

    int stride = gridDim.x * blockDim.x;
    for (int pair = blockIdx.x*blockDim.x + threadIdx.x; pair < PAIRS; pair += stride) {
        int n   = pair >> 4;
        int nbr = idx[pair];
        float d0 = p[nbr*3+0] - p[n*3+0];
        float d1 = p[nbr*3+1] - p[n*3+1];
        float d2 = p[nbr*3+2] - p[n*3+2];
        float v0 = b0 + d0*w00 + d1*w10 + d2*w20;
        float v1 = b1 + d0*w01 + d1*w11 + d2*w21;
        float v2 = b2 + d0*w02 + d1*w12 + d2*w22;
        g_prlin[pair*3+0] = v0;
        g_prlin[pair*3+1] = v1;
        g_prlin[pair*3+2] = v2;
        s[0] += v0; ss[0] += v0*v0;
        s[1] += v1; ss[1] += v1*v1;
        s[2] += v2; ss[2] += v2*v2;
    }

#pragma unroll
    for (int o = 16; o > 0; o >>= 1) {
#pragma unroll
        for (int j = 0; j < 3; j++) {
            s[j]  += __shfl_down_sync(0xffffffffu, s[j],  o);
            ss[j] += __shfl_down_sync(0xffffffffu, ss[j], o);
        }
    }
    __shared__ float part[8][6];
    int lane = threadIdx.x & 31, w = threadIdx.x >> 5;
    if (lane == 0) {
        part[w][0] = s[0];  part[w][1] = s[1];  part[w][2] = s[2];
        part[w][3] = ss[0]; part[w][4] = ss[1]; part[w][5] = ss[2];
    }
    __syncthreads();
    if (threadIdx.x < 6) {
        float tot = 0.f;
#pragma unroll
        for (int ww = 0; ww < 8; ww++) tot += part[ww][threadIdx.x];
        if (threadIdx.x < 3) atomicAdd(&g_s1[threadIdx.x], tot);
        else                 atomicAdd(&g_ss1[threadIdx.x - 3], tot);
    }
    // fused finalize (last block)
    __syncthreads();
    __shared__ bool is_last;
    if (threadIdx.x == 0) {
        __threadfence();
        is_last = (atomicAdd(&g_tk1, 1u) == gridDim.x - 1);
    }
    __syncthreads();
    if (is_last && threadIdx.x < 3) {
        __threadfence();
        int c = threadIdx.x;
        float cnt = (float)PAIRS;
        float mean = g_s1[c] / cnt;
        float var  = g_ss1[c] / cnt - mean*mean;
        float scv  = g[c] * rsqrtf(var + FEPS);
        g_scale1[c] = scv;
        g_shift1[c] = be[c] - mean*scv;
    }
}

// ---------------- K4: BN2 stats (R1 scalar form) + fused finalize -----------
__global__ void k_bn2stats(const int* __restrict__ idx,
                           const float* __restrict__ pW2, const float* __restrict__ pb2,
                           const float* __restrict__ g, const float* __restrict__ be) {
    int t = threadIdx.x, lane = t & 31, w = t >> 5;
    int wg = blockIdx.x*8 + w;

    float4 pw0  = *(const float4*)&pW2[0*CDIM + lane*4];
    float4 pw1  = *(const float4*)&pW2[1*CDIM + lane*4];
    float4 pw2v = *(const float4*)&pW2[2*CDIM + lane*4];
    float4 pbv  = *(const float4*)&pb2[lane*4];
    float sc0 = g_scale1[0], sc1 = g_scale1[1], sc2 = g_scale1[2];
    float sh0 = g_shift1[0], sh1 = g_shift1[1], sh2 = g_shift1[2];

    const float4* kp = (const float4*)g_k;
    const float4* qp = (const float4*)g_q;

    float4 s4  = {0.f,0.f,0.f,0.f};
    float4 q4s = {0.f,0.f,0.f,0.f};

    int base = wg*128;
    for (int i = 0; i < 128; i++) {
        int pair = base + i;
        int n    = pair >> 4;
        int nbr  = idx[pair];
        float h0 = fmaxf(g_prlin[pair*3+0]*sc0 + sh0, 0.f);
        float h1 = fmaxf(g_prlin[pair*3+1]*sc1 + sh1, 0.f);
        float h2 = fmaxf(g_prlin[pair*3+2]*sc2 + sh2, 0.f);
        float4 kk = kp[nbr*32 + lane];
        float4 qq = qp[n*32 + lane];
        float wx = kk.x - qq.x + pbv.x + h0*pw0.x + h1*pw1.x + h2*pw2v.x;
        float wy = kk.y - qq.y + pbv.y + h0*pw0.y + h1*pw1.y + h2*pw2v.y;
        float wz = kk.z - qq.z + pbv.z + h0*pw0.z + h1*pw1.z + h2*pw2v.z;
        float ww = kk.w - qq.w + pbv.w + h0*pw0.w + h1*pw1.w + h2*pw2v.w;
        s4.x += wx; q4s.x += wx*wx;
        s4.y += wy; q4s.y += wy*wy;
        s4.z += wz; q4s.z += wz*wz;
        s4.w += ww; q4s.w += ww*ww;
    }

    __shared__ float red[8][256];
    red[w][lane*4+0]     = s4.x;  red[w][lane*4+1]     = s4.y;
    red[w][lane*4+2]     = s4.z;  red[w][lane*4+3]     = s4.w;
    red[w][128+lane*4+0] = q4s.x; red[w][128+lane*4+1] = q4s.y;
    red[w][128+lane*4+2] = q4s.z; red[w][128+lane*4+3] = q4s.w;
    __syncthreads();
    float tot = 0.f;
#pragma unroll
    for (int ww = 0; ww < 8; ww++) tot += red[ww][t];
    if (t < 128) atomicAdd(&g_s2[t], tot);
    else         atomicAdd(&g_ss2[t-128], tot);

    // fused finalize (last block)
    __syncthreads();
    __shared__ bool is_last;
    if (t == 0) {
        __threadfence();
        is_last = (atomicAdd(&g_tk2, 1u) == gridDim.x - 1);
    }
    __syncthreads();
    if (is_last && t < CDIM) {
        __threadfence();
        float cnt = (float)PAIRS;
        float mean = g_s2[t] / cnt;
        float var  = g_ss2[t] / cnt - mean*mean;
        float scv  = g[t] * rsqrtf(var + FEPS);
        g_scale2[t] = scv;
        g_shift2[t] = be[t] - mean*scv;
    }
}

// ---------------- K5: w2 = relu(bn2(w)) @ wW1 + wb1 + BN3 stats + finalize --
// R1 stage A (scalar, 4 independent chains). Stage B: f32x2 experiment.
__global__ void k_w2(const int* __restrict__ idx,
                     const float* __restrict__ pW2, const float* __restrict__ pb2,
                     const float* __restrict__ wW1, const float* __restrict__ wb1,
                     const float* __restrict__ g, const float* __restrict__ be) {
    __shared__ float us[64*132];
    __shared__ float wt[16*132];          // transposed wW1: wt[j][c]
    __shared__ float s3s[CSD], ss3s[CSD];

    int t = threadIdx.x, lane = t & 31, w = t >> 5;

    for (int e = t; e < 128*16; e += 256)
        wt[(e & 15)*132 + (e >> 4)] = wW1[e];     // wW1[c*16+j] -> wt[j][c]
    if (t < CSD) { s3s[t] = 0.f; ss3s[t] = 0.f; }

    float4 pw0  = *(const float4*)&pW2[0*CDIM + lane*4];
    float4 pw1  = *(const float4*)&pW2[1*CDIM + lane*4];
    float4 pw2v = *(const float4*)&pW2[2*CDIM + lane*4];
    float4 pbv  = *(const float4*)&pb2[lane*4];
    float4 s2c  = *(const float4*)&g_scale2[lane*4];
    float4 h2c  = *(const float4*)&g_shift2[lane*4];
    float sc0 = g_scale1[0], sc1 = g_scale1[1], sc2 = g_scale1[2];
    float sh0 = g_shift1[0], sh1 = g_shift1[1], sh2 = g_shift1[2];

    const float4* kp = (const float4*)g_k;
    const float4* qp = (const float4*)g_q;

    int p_ = t >> 2, q_ = t & 3;
    float bj[4];
#pragma unroll
    for (int jj = 0; jj < 4; jj++) bj[jj] = wb1[q_*4 + jj];

    float ls[4]  = {0.f,0.f,0.f,0.f};
    float lss[4] = {0.f,0.f,0.f,0.f};

    __syncthreads();

    for (int ti = 0; ti < 8; ti++) {
        int tile = blockIdx.x*8 + ti;
        // stage A: build u for 64 pairs (scalar, 4 independent FMA chains)
#pragma unroll
        for (int pi = 0; pi < 8; pi++) {
            int prl  = w*8 + pi;
            int pair = tile*64 + prl;
            int n    = pair >> 4;
            int nbr  = idx[pair];
            float h0 = fmaxf(g_prlin[pair*3+0]*sc0 + sh0, 0.f);
            float h1 = fmaxf(g_prlin[pair*3+1]*sc1 + sh1, 0.f);
            float h2 = fmaxf(g_prlin[pair*3+2]*sc2 + sh2, 0.f);
            float4 kk = kp[nbr*32 + lane];
            float4 qq = qp[n*32 + lane];
            float4 u;
            u.x = fmaxf((kk.x - qq.x + pbv.x + h0*pw0.x + h1*pw1.x + h2*pw2v.x)*s2c.x + h2c.x, 0.f);
            u.y = fmaxf((kk.y - qq.y + pbv.y + h0*pw0.y + h1*pw1.y + h2*pw2v.y)*s2c.y + h2c.y, 0.f);
            u.z = fmaxf((kk.z - qq.z + pbv.z + h0*pw0.z + h1*pw1.z + h2*pw2v.z)*s2c.z + h2c.z, 0.f);
            u.w = fmaxf((kk.w - qq.w + pbv.w + h0*pw0.w + h1*pw1.w + h2*pw2v.w)*s2c.w + h2c.w, 0.f);
            *(float4*)&us[prl*132 + lane*4] = u;
        }
        __syncthreads();

        // stage B: 128 -> 16 dot; f32x2 packed along K (the FFMA2 experiment)
        ull acc[4] = {0ull, 0ull, 0ull, 0ull};
#pragma unroll 8
        for (int c = 0; c < 128; c += 4) {
            double2 ud = *(const double2*)&us[p_*132 + c];
            ull u01 = D2L(ud.x), u23 = D2L(ud.y);
#pragma unroll
            for (int jj = 0; jj < 4; jj++) {
                double2 wd = *(const double2*)&wt[(q_*4 + jj)*132 + c];
                fma2(acc[jj], u01, D2L(wd.x));
                fma2(acc[jj], u23, D2L(wd.y));
            }
        }
        int pair = tile*64 + p_;
        float4 o;
        {
            float lo, hi;
            upk2(lo, hi, acc[0]); o.x = lo + hi + bj[0];
            upk2(lo, hi, acc[1]); o.y = lo + hi + bj[1];
            upk2(lo, hi, acc[2]); o.z = lo + hi + bj[2];
            upk2(lo, hi, acc[3]); o.w = lo + hi + bj[3];
        }
        *(float4*)&g_w2[pair*16 + q_*4] = o;
        ls[0] += o.x; lss[0] += o.x*o.x;
        ls[1] += o.y; lss[1] += o.y*o.y;
        ls[2] += o.z; lss[2] += o.z*o.z;
        ls[3] += o.w; lss[3] += o.w*o.w;
        __syncthreads();
    }

    atomicAdd(&s3s[q_*4+0], ls[0]);  atomicAdd(&ss3s[q_*4+0], lss[0]);
    atomicAdd(&s3s[q_*4+1], ls[1]);  atomicAdd(&ss3s[q_*4+1], lss[1]);
    atomicAdd(&s3s[q_*4+2], ls[2]);  atomicAdd(&ss3s[q_*4+2], lss[2]);
    atomicAdd(&s3s[q_*4+3], ls[3]);  atomicAdd(&ss3s[q_*4+3], lss[3]);
    __syncthreads();
    if (t < CSD)        atomicAdd(&g_s3[t], s3s[t]);
    else if (t < 2*CSD) atomicAdd(&g_ss3[t-CSD], ss3s[t-CSD]);

    // fused finalize (last block)
    __syncthreads();
    __shared__ bool is_last;
    if (t == 0) {
        __threadfence();
        is_last = (atomicAdd(&g_tk3, 1u) == gridDim.x - 1);
    }
    __syncthreads();
    if (is_last && t < CSD) {
        __threadfence();
        float cnt = (float)PAIRS;
        float mean = g_s3[t] / cnt;
        float var  = g_ss3[t] / cnt - mean*mean;
        float scv  = g[t] * rsqrtf(var + FEPS);
        g_scale3[t] = scv;
        g_shift3[t] = be[t] - mean*scv;
    }
}

// ---------------- K6: bn3 + 16x16 matmul + softmax + aggregate --------------
__global__ void k_final(const int* __restrict__ idx,
                        const float* __restrict__ pW2, const float* __restrict__ pb2,
                        const float* __restrict__ wW2, const float* __restrict__ wb2,
                        float* __restrict__ out) {
    int n = blockIdx.x;
    int t = threadIdx.x;

    __shared__ float a[16*17];
    __shared__ float wsm[16*17];
    __shared__ float hs[16][4];
    __shared__ int   nbrs[16];

    if (t < 16) {
        int pair = n*16 + t;
        nbrs[t]  = idx[pair];
        hs[t][0] = fmaxf(g_prlin[pair*3+0]*g_scale1[0] + g_shift1[0], 0.f);
        hs[t][1] = fmaxf(g_prlin[pair*3+1]*g_scale1[1] + g_shift1[1], 0.f);
        hs[t][2] = fmaxf(g_prlin[pair*3+2]*g_scale1[2] + g_shift1[2], 0.f);
    }

#pragma unroll
    for (int i = t; i < 256; i += 128) {
        int c2 = i & 15;
        float v = g_w2[n*256 + i];
        a[(i >> 4)*17 + c2] = fmaxf(v*g_scale3[c2] + g_shift3[c2], 0.f);
    }
    __syncthreads();

#pragma unroll
    for (int i = t; i < 256; i += 128) {
        int s = i >> 4, c2 = i & 15;
        float acc = wb2[c2];
#pragma unroll
        for (int j = 0; j < 16; j++) acc += a[s*17 + j] * wW2[j*16 + c2];
        wsm[s*17 + c2] = acc;
    }
    __syncthreads();

    if (t < 16) {
        float m = -1e30f;
#pragma unroll
        for (int s = 0; s < 16; s++) m = fmaxf(m, wsm[s*17 + t]);
        float e[16]; float sum = 0.f;
#pragma unroll
        for (int s = 0; s < 16; s++) { e[s] = __expf(wsm[s*17 + t] - m); sum += e[s]; }
        float inv = 1.f / sum;
#pragma unroll
        for (int s = 0; s < 16; s++) wsm[s*17 + t] = e[s] * inv;
    }
    __syncthreads();

    int c = t, c2 = t & 15;
    float pb2c = pb2[c];
    float pw0 = pW2[c], pw1 = pW2[128 + c], pw2 = pW2[256 + c];
    float acc = 0.f;
#pragma unroll
    for (int s = 0; s < 16; s++) {
        float vv  = g_v[nbrs[s]*128 + c];
        float pr1 = pb2c + hs[s][0]*pw0 + hs[s][1]*pw1 + hs[s][2]*pw2;
        acc += (vv + pr1) * wsm[s*17 + c2];
    }
    out[n*128 + c] = acc;
}

// ---------------- launch -----------------------------------------------------
extern "C" void kernel_launch(void* const* d_in, const int* in_sizes, int n_in,
                              void* d_out, int out_size) {
    (void)in_sizes; (void)n_in; (void)out_size;
    const float* p    = (const float*)d_in[0];
    const float* x    = (const float*)d_in[1];
    const float* Wq   = (const float*)d_in[2];
    const float* bq   = (const float*)d_in[3];
    const float* Wk   = (const float*)d_in[4];
    const float* bk   = (const float*)d_in[5];
    const float* Wv   = (const float*)d_in[6];
    const float* bv   = (const float*)d_in[7];
    const float* pW1  = (const float*)d_in[8];
    const float* pb1  = (const float*)d_in[9];
    const float* pg1  = (const float*)d_in[10];
    const float* pbe1 = (const float*)d_in[11];
    const float* pW2  = (const float*)d_in[12];
    const float* pb2  = (const float*)d_in[13];
    const float* wg1  = (const float*)d_in[14];
    const float* wbe1 = (const float*)d_in[15];
    const float* wW1  = (const float*)d_in[16];
    const float* wb1  = (const float*)d_in[17];
    const float* wg2  = (const float*)d_in[18];
    const float* wbe2 = (const float*)d_in[19];
    const float* wW2  = (const float*)d_in[20];
    const float* wb2  = (const float*)d_in[21];
    const int*   idx  = (const int*)  d_in[22];
    float* out = (float*)d_out;

    k_zero<<<1, 128>>>();                                        // 1
    k_qkv<<<dim3(NPTS/64, 3), 256>>>(x, Wq, bq, Wk, bk, Wv, bv); // 2
    k_prlin<<<2048, 256>>>(p, idx, pW1, pb1, pg1, pbe1);         // 3
    k_bn2stats<<<512, 256>>>(idx, pW2, pb2, wg1, wbe1);          // 4
    k_w2<<<1024, 256>>>(idx, pW2, pb2, wW1, wb1, wg2, wbe2);     // 5
    k_final<<<NPTS, 128>>>(idx, pW2, pb2, wW2, wb2, out);        // 6
}

// round 4
// speedup vs baseline: 1.4373x; 1.4373x over previous
#include <cuda_runtime.h>

#define NPTS 32768
#define CDIM 128
#define NSAM 16
#define CSD  16
#define PAIRS (NPTS*NSAM)
#define FEPS 1e-5f

// ---------------- scratch (device globals; no allocation allowed) ----------
__device__ float g_q[NPTS*CDIM];
__device__ float g_k[NPTS*CDIM];
__device__ float g_v[NPTS*CDIM];
__device__ float g_prlin[PAIRS*3];
__device__ float g_w2[PAIRS*CSD];

__device__ float g_s1[3],    g_ss1[3],    g_scale1[3],    g_shift1[3];
__device__ float g_s2[CDIM], g_ss2[CDIM], g_scale2[CDIM], g_shift2[CDIM];
__device__ float g_s3[CSD],  g_ss3[CSD],  g_scale3[CSD],  g_shift3[CSD];
__device__ unsigned g_tk1, g_tk2, g_tk3;

// ---------------- K1: zero stats + tickets ----------------------------------
__global__ void k_zero() {
    int t = threadIdx.x;
    if (t < 3)    { g_s1[t] = 0.f; g_ss1[t] = 0.f; }
    if (t < CDIM) { g_s2[t] = 0.f; g_ss2[t] = 0.f; }
    if (t < CSD)  { g_s3[t] = 0.f; g_ss3[t] = 0.f; }
    if (t == 0) { g_tk1 = 0; g_tk2 = 0; g_tk3 = 0; }
}

// ---------------- K2: q/k/v GEMMs, 128x128 block tile, 8x8 thread tile ------
// grid (N/128, 3), block 256. BK=8. Both operands via LDS.128.
__global__ __launch_bounds__(256)
void k_qkv(const float* __restrict__ x,
           const float* __restrict__ Wq, const float* __restrict__ bq,
           const float* __restrict__ Wk, const float* __restrict__ bk,
           const float* __restrict__ Wv, const float* __restrict__ bv) {
    const float* W; const float* b; float* out;
    if (blockIdx.y == 0)      { W = Wq; b = bq; out = g_q; }
    else if (blockIdx.y == 1) { W = Wk; b = bk; out = g_k; }
    else                      { W = Wv; b = bv; out = g_v; }

    __shared__ float xs[8*132];   // [k][row], k-major (transposed on store)
    __shared__ float ws[8*132];   // [k][col]

    int t  = threadIdx.x;
    int tx = t & 15, ty = t >> 4;
    int row0 = blockIdx.x * 128;

    float acc[8][8];
#pragma unroll
    for (int i = 0; i < 8; i++)
#pragma unroll
        for (int j = 0; j < 8; j++) acc[i][j] = 0.f;

    int xr  = t >> 1;            // 0..127
    int xk4 = (t & 1) * 4;       // 0 or 4
    int wk  = t >> 5;            // 0..7
    int wc  = (t & 31) * 4;

    for (int kb = 0; kb < 128; kb += 8) {
        float4 xv = *(const float4*)&x[(row0 + xr)*128 + kb + xk4];
        xs[(xk4+0)*132 + xr] = xv.x;
        xs[(xk4+1)*132 + xr] = xv.y;
        xs[(xk4+2)*132 + xr] = xv.z;
        xs[(xk4+3)*132 + xr] = xv.w;
        *(float4*)&ws[wk*132 + wc] = *(const float4*)&W[(kb + wk)*128 + wc];
        __syncthreads();
#pragma unroll
        for (int k = 0; k < 8; k++) {
            float4 a0 = *(const float4*)&xs[k*132 + ty*4];
            float4 a1 = *(const float4*)&xs[k*132 + 64 + ty*4];
            float4 b0 = *(const float4*)&ws[k*132 + tx*4];
            float4 b1 = *(const float4*)&ws[k*132 + 64 + tx*4];
            float ar[8] = {a0.x,a0.y,a0.z,a0.w,a1.x,a1.y,a1.z,a1.w};
            float br[8] = {b0.x,b0.y,b0.z,b0.w,b1.x,b1.y,b1.z,b1.w};
#pragma unroll
            for (int i = 0; i < 8; i++)
#pragma unroll
                for (int j = 0; j < 8; j++) acc[i][j] += ar[i]*br[j];
        }
        __syncthreads();
    }

    float4 bj0 = *(const float4*)&b[tx*4];
    float4 bj1 = *(const float4*)&b[64 + tx*4];
    float bb[8] = {bj0.x,bj0.y,bj0.z,bj0.w,bj1.x,bj1.y,bj1.z,bj1.w};
#pragma unroll
    for (int i = 0; i < 8; i++) {
        int r = row0 + (i < 4 ? ty*4 + i : 64 + ty*4 + (i-4));
        float4 o0, o1;
        o0.x = acc[i][0]+bb[0]; o0.y = acc[i][1]+bb[1];
        o0.z = acc[i][2]+bb[2]; o0.w = acc[i][3]+bb[3];
        o1.x = acc[i][4]+bb[4]; o1.y = acc[i][5]+bb[5];
        o1.z = acc[i][6]+bb[6]; o1.w = acc[i][7]+bb[7];
        *(float4*)&out[r*128 + tx*4]      = o0;
        *(float4*)&out[r*128 + 64 + tx*4] = o1;
    }
}

// ---------------- K3: prlin + BN1 stats + fused finalize --------------------
__global__ void k_prlin(const float* __restrict__ p, const int* __restrict__ idx,
                        const float* __restrict__ pW1, const float* __restrict__ pb1,
                        const float* __restrict__ g, const float* __restrict__ be) {
    float w00 = pW1[0], w01 = pW1[1], w02 = pW1[2];
    float w10 = pW1[3], w11 = pW1[4], w12 = pW1[5];
    float w20 = pW1[6], w21 = pW1[7], w22 = pW1[8];
    float b0 = pb1[0], b1 = pb1[1], b2 = pb1[2];

    float s[3]  = {0.f, 0.f, 0.f};
    float ss[3] = {0.f, 0.f, 0.f};

    int stride = gridDim.x * blockDim.x;
    for (int pair = blockIdx.x*blockDim.x + threadIdx.x; pair < PAIRS; pair += stride) {
        int n   = pair >> 4;
        int nbr = idx[pair];
        float d0 = p[nbr*3+0] - p[n*3+0];
        float d1 = p[nbr*3+1] - p[n*3+1];
        float d2 = p[nbr*3+2] - p[n*3+2];
        float v0 = b0 + d0*w00 + d1*w10 + d2*w20;
        float v1 = b1 + d0*w01 + d1*w11 + d2*w21;
        float v2 = b2 + d0*w02 + d1*w12 + d2*w22;
        g_prlin[pair*3+0] = v0;
        g_prlin[pair*3+1] = v1;
        g_prlin[pair*3+2] = v2;
        s[0] += v0; ss[0] += v0*v0;
        s[1] += v1; ss[1] += v1*v1;
        s[2] += v2; ss[2] += v2*v2;
    }

#pragma unroll
    for (int o = 16; o > 0; o >>= 1) {
#pragma unroll
        for (int j = 0; j < 3; j++) {
            s[j]  += __shfl_down_sync(0xffffffffu, s[j],  o);
            ss[j] += __shfl_down_sync(0xffffffffu, ss[j], o);
        }
    }
    __shared__ float part[8][6];
    int lane = threadIdx.x & 31, w = threadIdx.x >> 5;
    if (lane == 0) {
        part[w][0] = s[0];  part[w][1] = s[1];  part[w][2] = s[2];
        part[w][3] = ss[0]; part[w][4] = ss[1]; part[w][5] = ss[2];
    }
    __syncthreads();
    if (threadIdx.x < 6) {
        float tot = 0.f;
#pragma unroll
        for (int ww = 0; ww < 8; ww++) tot += part[ww][threadIdx.x];
        if (threadIdx.x < 3) atomicAdd(&g_s1[threadIdx.x], tot);
        else                 atomicAdd(&g_ss1[threadIdx.x - 3], tot);
    }
    // fused finalize (last block)
    __syncthreads();
    __shared__ bool is_last;
    if (threadIdx.x == 0) {
        __threadfence();
        is_last = (atomicAdd(&g_tk1, 1u) == gridDim.x - 1);
    }
    __syncthreads();
    if (is_last && threadIdx.x < 3) {
        __threadfence();
        int c = threadIdx.x;
        float cnt = (float)PAIRS;
        float mean = g_s1[c] / cnt;
        float var  = g_ss1[c] / cnt - mean*mean;
        float scv  = g[c] * rsqrtf(var + FEPS);
        g_scale1[c] = scv;
        g_shift1[c] = be[c] - mean*scv;
    }
}

// ---------------- K4: BN2 stats + fused finalize. grid 2048 (occupancy) -----
__global__ void k_bn2stats(const int* __restrict__ idx,
                           const float* __restrict__ pW2, const float* __restrict__ pb2,
                           const float* __restrict__ g, const float* __restrict__ be) {
    int t = threadIdx.x, lane = t & 31, w = t >> 5;
    int wg = blockIdx.x*8 + w;            // 0..16383, 32 pairs each

    float4 pw0  = *(const float4*)&pW2[0*CDIM + lane*4];
    float4 pw1  = *(const float4*)&pW2[1*CDIM + lane*4];
    float4 pw2v = *(const float4*)&pW2[2*CDIM + lane*4];
    float4 pbv  = *(const float4*)&pb2[lane*4];
    float sc0 = g_scale1[0], sc1 = g_scale1[1], sc2 = g_scale1[2];
    float sh0 = g_shift1[0], sh1 = g_shift1[1], sh2 = g_shift1[2];

    const float4* kp = (const float4*)g_k;
    const float4* qp = (const float4*)g_q;

    float4 s4  = {0.f,0.f,0.f,0.f};
    float4 q4s = {0.f,0.f,0.f,0.f};

    int base = wg*32;
    for (int i = 0; i < 32; i++) {
        int pair = base + i;
        int n    = pair >> 4;
        int nbr  = idx[pair];
        float h0 = fmaxf(g_prlin[pair*3+0]*sc0 + sh0, 0.f);
        float h1 = fmaxf(g_prlin[pair*3+1]*sc1 + sh1, 0.f);
        float h2 = fmaxf(g_prlin[pair*3+2]*sc2 + sh2, 0.f);
        float4 kk = kp[nbr*32 + lane];
        float4 qq = qp[n*32 + lane];
        float wx = kk.x - qq.x + pbv.x + h0*pw0.x + h1*pw1.x + h2*pw2v.x;
        float wy = kk.y - qq.y + pbv.y + h0*pw0.y + h1*pw1.y + h2*pw2v.y;
        float wz = kk.z - qq.z + pbv.z + h0*pw0.z + h1*pw1.z + h2*pw2v.z;
        float ww = kk.w - qq.w + pbv.w + h0*pw0.w + h1*pw1.w + h2*pw2v.w;
        s4.x += wx; q4s.x += wx*wx;
        s4.y += wy; q4s.y += wy*wy;
        s4.z += wz; q4s.z += wz*wz;
        s4.w += ww; q4s.w += ww*ww;
    }

    __shared__ float red[8][256];
    red[w][lane*4+0]     = s4.x;  red[w][lane*4+1]     = s4.y;
    red[w][lane*4+2]     = s4.z;  red[w][lane*4+3]     = s4.w;
    red[w][128+lane*4+0] = q4s.x; red[w][128+lane*4+1] = q4s.y;
    red[w][128+lane*4+2] = q4s.z; red[w][128+lane*4+3] = q4s.w;
    __syncthreads();
    float tot = 0.f;
#pragma unroll
    for (int ww = 0; ww < 8; ww++) tot += red[ww][t];
    if (t < 128) atomicAdd(&g_s2[t], tot);
    else         atomicAdd(&g_ss2[t-128], tot);

    // fused finalize (last block)
    __syncthreads();
    __shared__ bool is_last;
    if (t == 0) {
        __threadfence();
        is_last = (atomicAdd(&g_tk2, 1u) == gridDim.x - 1);
    }
    __syncthreads();
    if (is_last && t < CDIM) {
        __threadfence();
        float cnt = (float)PAIRS;
        float mean = g_s2[t] / cnt;
        float var  = g_ss2[t] / cnt - mean*mean;
        float scv  = g[t] * rsqrtf(var + FEPS);
        g_scale2[t] = scv;
        g_shift2[t] = be[t] - mean*scv;
    }
}

// ---------------- K5: w2 = relu(bn2(w)) @ wW1 + wb1 + BN3 stats + finalize --
// R1 scalar form throughout. block 256, 8 tiles of 64 pairs, grid 1024.
__global__ __launch_bounds__(256, 2)
void k_w2(const int* __restrict__ idx,
          const float* __restrict__ pW2, const float* __restrict__ pb2,
          const float* __restrict__ wW1, const float* __restrict__ wb1,
          const float* __restrict__ g, const float* __restrict__ be) {
    __shared__ float us[64*132];
    __shared__ float wW1s[128*20];
    __shared__ float s3s[CSD], ss3s[CSD];

    int t = threadIdx.x, lane = t & 31, w = t >> 5;

    for (int e = t; e < 128*16; e += 256)
        wW1s[(e >> 4)*20 + (e & 15)] = wW1[e];
    if (t < CSD) { s3s[t] = 0.f; ss3s[t] = 0.f; }

    float4 pw0  = *(const float4*)&pW2[0*CDIM + lane*4];
    float4 pw1  = *(const float4*)&pW2[1*CDIM + lane*4];
    float4 pw2v = *(const float4*)&pW2[2*CDIM + lane*4];
    float4 pbv  = *(const float4*)&pb2[lane*4];
    float4 s2c  = *(const float4*)&g_scale2[lane*4];
    float4 h2c  = *(const float4*)&g_shift2[lane*4];
    float sc0 = g_scale1[0], sc1 = g_scale1[1], sc2 = g_scale1[2];
    float sh0 = g_shift1[0], sh1 = g_shift1[1], sh2 = g_shift1[2];

    const float4* kp = (const float4*)g_k;
    const float4* qp = (const float4*)g_q;

    int p_ = t >> 2, q_ = t & 3;
    float4 bq4 = *(const float4*)&wb1[q_*4];

    float ls[4]  = {0.f,0.f,0.f,0.f};
    float lss[4] = {0.f,0.f,0.f,0.f};

    __syncthreads();

    for (int ti = 0; ti < 8; ti++) {
        int tile = blockIdx.x*8 + ti;
        // stage A: build u for 64 pairs
#pragma unroll
        for (int pi = 0; pi < 8; pi++) {
            int prl  = w*8 + pi;
            int pair = tile*64 + prl;
            int n    = pair >> 4;
            int nbr  = idx[pair];
            float h0 = fmaxf(g_prlin[pair*3+0]*sc0 + sh0, 0.f);
            float h1 = fmaxf(g_prlin[pair*3+1]*sc1 + sh1, 0.f);
            float h2 = fmaxf(g_prlin[pair*3+2]*sc2 + sh2, 0.f);
            float4 kk = kp[nbr*32 + lane];
            float4 qq = qp[n*32 + lane];
            float4 u;
            u.x = fmaxf((kk.x - qq.x + pbv.x + h0*pw0.x + h1*pw1.x + h2*pw2v.x)*s2c.x + h2c.x, 0.f);
            u.y = fmaxf((kk.y - qq.y + pbv.y + h0*pw0.y + h1*pw1.y + h2*pw2v.y)*s2c.y + h2c.y, 0.f);
            u.z = fmaxf((kk.z - qq.z + pbv.z + h0*pw0.z + h1*pw1.z + h2*pw2v.z)*s2c.z + h2c.z, 0.f);
            u.w = fmaxf((kk.w - qq.w + pbv.w + h0*pw0.w + h1*pw1.w + h2*pw2v.w)*s2c.w + h2c.w, 0.f);
            *(float4*)&us[prl*132 + lane*4] = u;
        }
        __syncthreads();

        // stage B: 128 -> 16 dot, 4 outputs per thread (scalar, R1 form)
        float4 acc = bq4;
#pragma unroll 16
        for (int c = 0; c < 128; c++) {
            float  uu = us[p_*132 + c];
            float4 wv = *(const float4*)&wW1s[c*20 + q_*4];
            acc.x += uu*wv.x; acc.y += uu*wv.y;
            acc.z += uu*wv.z; acc.w += uu*wv.w;
        }
        int pair = tile*64 + p_;
        *(float4*)&g_w2[pair*16 + q_*4] = acc;
        ls[0] += acc.x; lss[0] += acc.x*acc.x;
        ls[1] += acc.y; lss[1] += acc.y*acc.y;
        ls[2] += acc.z; lss[2] += acc.z*acc.z;
        ls[3] += acc.w; lss[3] += acc.w*acc.w;
        __syncthreads();
    }

    atomicAdd(&s3s[q_*4+0], ls[0]);  atomicAdd(&ss3s[q_*4+0], lss[0]);
    atomicAdd(&s3s[q_*4+1], ls[1]);  atomicAdd(&ss3s[q_*4+1], lss[1]);
    atomicAdd(&s3s[q_*4+2], ls[2]);  atomicAdd(&ss3s[q_*4+2], lss[2]);
    atomicAdd(&s3s[q_*4+3], ls[3]);  atomicAdd(&ss3s[q_*4+3], lss[3]);
    __syncthreads();
    if (t < CSD)        atomicAdd(&g_s3[t], s3s[t]);
    else if (t < 2*CSD) atomicAdd(&g_ss3[t-CSD], ss3s[t-CSD]);

    // fused finalize (last block)
    __syncthreads();
    __shared__ bool is_last;
    if (t == 0) {
        __threadfence();
        is_last = (atomicAdd(&g_tk3, 1u) == gridDim.x - 1);
    }
    __syncthreads();
    if (is_last && t < CSD) {
        __threadfence();
        float cnt = (float)PAIRS;
        float mean = g_s3[t] / cnt;
        float var  = g_ss3[t] / cnt - mean*mean;
        float scv  = g[t] * rsqrtf(var + FEPS);
        g_scale3[t] = scv;
        g_shift3[t] = be[t] - mean*scv;
    }
}

// ---------------- K6: bn3 + 16x16 matmul + softmax + aggregate --------------
__global__ void k_final(const int* __restrict__ idx,
                        const float* __restrict__ pW2, const float* __restrict__ pb2,
                        const float* __restrict__ wW2, const float* __restrict__ wb2,
                        float* __restrict__ out) {
    int n = blockIdx.x;
    int t = threadIdx.x;

    __shared__ float a[16*17];
    __shared__ float wsm[16*17];
    __shared__ float hs[16][4];
    __shared__ int   nbrs[16];

    if (t < 16) {
        int pair = n*16 + t;
        nbrs[t]  = idx[pair];
        hs[t][0] = fmaxf(g_prlin[pair*3+0]*g_scale1[0] + g_shift1[0], 0.f);
        hs[t][1] = fmaxf(g_prlin[pair*3+1]*g_scale1[1] + g_shift1[1], 0.f);
        hs[t][2] = fmaxf(g_prlin[pair*3+2]*g_scale1[2] + g_shift1[2], 0.f);
    }

#pragma unroll
    for (int i = t; i < 256; i += 128) {
        int c2 = i & 15;
        float v = g_w2[n*256 + i];
        a[(i >> 4)*17 + c2] = fmaxf(v*g_scale3[c2] + g_shift3[c2], 0.f);
    }
    __syncthreads();

#pragma unroll
    for (int i = t; i < 256; i += 128) {
        int s = i >> 4, c2 = i & 15;
        float acc = wb2[c2];
#pragma unroll
        for (int j = 0; j < 16; j++) acc += a[s*17 + j] * wW2[j*16 + c2];
        wsm[s*17 + c2] = acc;
    }
    __syncthreads();

    if (t < 16) {
        float m = -1e30f;
#pragma unroll
        for (int s = 0; s < 16; s++) m = fmaxf(m, wsm[s*17 + t]);
        float e[16]; float sum = 0.f;
#pragma unroll
        for (int s = 0; s < 16; s++) { e[s] = __expf(wsm[s*17 + t] - m); sum += e[s]; }
        float inv = 1.f / sum;
#pragma unroll
        for (int s = 0; s < 16; s++) wsm[s*17 + t] = e[s] * inv;
    }
    __syncthreads();

    int c = t, c2 = t & 15;
    float pb2c = pb2[c];
    float pw0 = pW2[c], pw1 = pW2[128 + c], pw2 = pW2[256 + c];
    float acc = 0.f;
#pragma unroll
    for (int s = 0; s < 16; s++) {
        float vv  = g_v[nbrs[s]*128 + c];
        float pr1 = pb2c + hs[s][0]*pw0 + hs[s][1]*pw1 + hs[s][2]*pw2;
        acc += (vv + pr1) * wsm[s*17 + c2];
    }
    out[n*128 + c] = acc;
}

// ---------------- launch -----------------------------------------------------
extern "C" void kernel_launch(void* const* d_in, const int* in_sizes, int n_in,
                              void* d_out, int out_size) {
    (void)in_sizes; (void)n_in; (void)out_size;
    const float* p    = (const float*)d_in[0];
    const float* x    = (const float*)d_in[1];
    const float* Wq   = (const float*)d_in[2];
    const float* bq   = (const float*)d_in[3];
    const float* Wk   = (const float*)d_in[4];
    const float* bk   = (const float*)d_in[5];
    const float* Wv   = (const float*)d_in[6];
    const float* bv   = (const float*)d_in[7];
    const float* pW1  = (const float*)d_in[8];
    const float* pb1  = (const float*)d_in[9];
    const float* pg1  = (const float*)d_in[10];
    const float* pbe1 = (const float*)d_in[11];
    const float* pW2  = (const float*)d_in[12];
    const float* pb2  = (const float*)d_in[13];
    const float* wg1  = (const float*)d_in[14];
    const float* wbe1 = (const float*)d_in[15];
    const float* wW1  = (const float*)d_in[16];
    const float* wb1  = (const float*)d_in[17];
    const float* wg2  = (const float*)d_in[18];
    const float* wbe2 = (const float*)d_in[19];
    const float* wW2  = (const float*)d_in[20];
    const float* wb2  = (const float*)d_in[21];
    const int*   idx  = (const int*)  d_in[22];
    float* out = (float*)d_out;

    k_zero<<<1, 128>>>();                                         // 1
    k_qkv<<<dim3(NPTS/128, 3), 256>>>(x, Wq, bq, Wk, bk, Wv, bv); // 2
    k_prlin<<<512, 256>>>(p, idx, pW1, pb1, pg1, pbe1);           // 3
    k_bn2stats<<<2048, 256>>>(idx, pW2, pb2, wg1, wbe1);          // 4
    k_w2<<<1024, 256>>>(idx, pW2, pb2, wW1, wb1, wg2, wbe2);      // 5
    k_final<<<NPTS, 128>>>(idx, pW2, pb2, wW2, wb2, out);         // 6
}